// round 1
// baseline (speedup 1.0000x reference)
#include <cuda_runtime.h>

// SAFM_2473901162526: the reference's sort/FFT/gelu branches are dead code
// (x_back == x exactly since argsort(argsort(p)) inverts the permutation and
// _dead is unused). Output reduces to a 1x1 conv:
//   out[b,o,p] = sum_c refine_w[o,c] * x[b,c,p] + refine_b[o]
// B=8, C=64, HW=65536 (fp32).

#define CC     64
#define HW     65536
#define BP     128          // pixels per block
#define NTHR   256          // 8 output-groups x 32 pixel-groups

__global__ __launch_bounds__(NTHR) void conv1x1_kernel(
    const float* __restrict__ x,
    const float* __restrict__ w,      // [64][64] row-major (o,c)
    const float* __restrict__ bias,   // [64]
    float* __restrict__ out)
{
    __shared__ float sh_x[CC * BP];     // 32 KB  [c][p]
    __shared__ float sh_w[CC * CC];     // 16 KB  [o][c] natural layout

    const int t  = threadIdx.x;
    const int b  = blockIdx.y;
    const int p0 = blockIdx.x * BP;
    const size_t xbase = (size_t)b * CC * HW + p0;

    // ---- stage x tile: 64c x 128p = 2048 float4, fully coalesced ----
#pragma unroll
    for (int k = 0; k < 8; k++) {
        int i  = t + k * NTHR;        // [0, 2048)
        int c  = i >> 5;              // 32 float4 per channel row
        int f4 = i & 31;
        float4 v = *(const float4*)(x + xbase + (size_t)c * HW + f4 * 4);
        *(float4*)(sh_x + c * BP + f4 * 4) = v;
    }
    // ---- stage weights (natural [o][c], coalesced, conflict-free) ----
#pragma unroll
    for (int k = 0; k < 4; k++) {
        int i = t + k * NTHR;         // [0, 4096) -> 4 x float4
        float4 v = *(const float4*)(w + i * 4);
        *(float4*)(sh_w + i * 4) = v;
    }
    __syncthreads();

    const int r = t >> 5;   // output group: owns o in {4r..4r+3} U {32+4r..32+4r+3}
    const int j = t & 31;   // pixel group:  owns p in {4j..4j+3}

    const float* wp0 = sh_w + (4 * r) * CC;        // rows 4r..4r+3
    const float* wp1 = sh_w + (32 + 4 * r) * CC;   // rows 32+4r..
    const float* xp  = sh_x + j * 4;

    float4 acc[8];
#pragma unroll
    for (int m = 0; m < 8; m++) acc[m] = make_float4(0.f, 0.f, 0.f, 0.f);

#define FMA4(A, S, V)                       \
    A.x = fmaf((S), (V).x, A.x);            \
    A.y = fmaf((S), (V).y, A.y);            \
    A.z = fmaf((S), (V).z, A.z);            \
    A.w = fmaf((S), (V).w, A.w);

#pragma unroll 8
    for (int c = 0; c < CC; c++) {
        float4 xv = *(const float4*)(xp + c * BP);          // LDS.128, conflict-free
        float w0 = wp0[0 * CC + c];                          // broadcast LDS
        float w1 = wp0[1 * CC + c];
        float w2 = wp0[2 * CC + c];
        float w3 = wp0[3 * CC + c];
        float w4 = wp1[0 * CC + c];
        float w5 = wp1[1 * CC + c];
        float w6 = wp1[2 * CC + c];
        float w7 = wp1[3 * CC + c];
        FMA4(acc[0], w0, xv);
        FMA4(acc[1], w1, xv);
        FMA4(acc[2], w2, xv);
        FMA4(acc[3], w3, xv);
        FMA4(acc[4], w4, xv);
        FMA4(acc[5], w5, xv);
        FMA4(acc[6], w6, xv);
        FMA4(acc[7], w7, xv);
    }

    // ---- epilogue: + bias, coalesced float4 stores ----
#pragma unroll
    for (int m = 0; m < 8; m++) {
        int o = (m < 4) ? (4 * r + m) : (32 + 4 * r + (m - 4));
        float bo = bias[o];
        float4 v = acc[m];
        v.x += bo; v.y += bo; v.z += bo; v.w += bo;
        *(float4*)(out + ((size_t)b * CC + o) * HW + p0 + j * 4) = v;
    }
}

extern "C" void kernel_launch(void* const* d_in, const int* in_sizes, int n_in,
                              void* d_out, int out_size)
{
    (void)in_sizes; (void)n_in; (void)out_size;
    const float* x    = (const float*)d_in[0];   // x
    const float* w    = (const float*)d_in[11];  // refine_w
    const float* bias = (const float*)d_in[12];  // refine_b
    float* out = (float*)d_out;

    dim3 grid(HW / BP, 8);   // 512 pixel tiles x 8 batches
    conv1x1_kernel<<<grid, NTHR>>>(x, w, bias, out);
}